// round 1
// baseline (speedup 1.0000x reference)
#include <cuda_runtime.h>
#include <math_constants.h>

// Problem constants
#define B_   8
#define LQ_  2048
#define LK_  2048
#define D_   1024
#define DV_  1024

// Scratch for qW = query @ W : [B*LQ, D] = 16384 x 1024 floats (64 MB)
__device__ float g_qW[(long)B_ * LQ_ * D_];

#define BM 128
#define BN 128
#define BK 8
#define TM 8
#define TN 8

// C[M,N] = A[M,K] @ op(B) (+ bias), batched via blockIdx.z strides.
// TRANS_B=false: B is [K,N] row-major.   TRANS_B=true: B is [N,K] row-major (C = A @ B^T).
template<bool TRANS_B, bool ADD_BIAS>
__global__ __launch_bounds__(256) void gemm_tile(
    const float* __restrict__ A, const float* __restrict__ Bm, float* __restrict__ C,
    int M, int N, int K,
    long sA, long sB, long sC,
    const float* __restrict__ bias)
{
    __shared__ float As[BK][BM];
    __shared__ float Bs[BK][BN];

    A  += (long)blockIdx.z * sA;
    Bm += (long)blockIdx.z * sB;
    C  += (long)blockIdx.z * sC;

    const int tid = threadIdx.x;
    const int tx  = tid & 15;   // 0..15  -> col group
    const int ty  = tid >> 4;   // 0..15  -> row group

    const int rowBlock = blockIdx.y * BM;
    const int colBlock = blockIdx.x * BN;

    // A-tile loader: 128 rows x 8 cols -> 256 float4 (2 threads/row)
    const int aRow  = tid >> 1;        // 0..127
    const int aCol4 = (tid & 1) * 4;   // 0 or 4
    // B-tile loader (NN): 8 rows x 128 cols -> 256 float4
    const int bRow  = tid >> 5;        // 0..7
    const int bCol4 = (tid & 31) * 4;  // 0..124

    float acc[TM][TN] = {};
    const float biasv = ADD_BIAS ? bias[0] : 0.0f;

    for (int k0 = 0; k0 < K; k0 += BK) {
        // Load A tile (store transposed: As[k][m])
        float4 av = *reinterpret_cast<const float4*>(
            &A[(long)(rowBlock + aRow) * K + k0 + aCol4]);
        As[aCol4 + 0][aRow] = av.x;
        As[aCol4 + 1][aRow] = av.y;
        As[aCol4 + 2][aRow] = av.z;
        As[aCol4 + 3][aRow] = av.w;

        if (TRANS_B) {
            // B is [N,K]; tile rows are C-columns
            float4 bv = *reinterpret_cast<const float4*>(
                &Bm[(long)(colBlock + aRow) * K + k0 + aCol4]);
            Bs[aCol4 + 0][aRow] = bv.x;
            Bs[aCol4 + 1][aRow] = bv.y;
            Bs[aCol4 + 2][aRow] = bv.z;
            Bs[aCol4 + 3][aRow] = bv.w;
        } else {
            float4 bv = *reinterpret_cast<const float4*>(
                &Bm[(long)(k0 + bRow) * N + colBlock + bCol4]);
            *reinterpret_cast<float4*>(&Bs[bRow][bCol4]) = bv;
        }
        __syncthreads();

        #pragma unroll
        for (int kk = 0; kk < BK; kk++) {
            float a[TM], b[TN];
            // vector LDS
            float4 a0 = *reinterpret_cast<const float4*>(&As[kk][ty * TM]);
            float4 a1 = *reinterpret_cast<const float4*>(&As[kk][ty * TM + 4]);
            float4 b0 = *reinterpret_cast<const float4*>(&Bs[kk][tx * TN]);
            float4 b1 = *reinterpret_cast<const float4*>(&Bs[kk][tx * TN + 4]);
            a[0]=a0.x; a[1]=a0.y; a[2]=a0.z; a[3]=a0.w;
            a[4]=a1.x; a[5]=a1.y; a[6]=a1.z; a[7]=a1.w;
            b[0]=b0.x; b[1]=b0.y; b[2]=b0.z; b[3]=b0.w;
            b[4]=b1.x; b[5]=b1.y; b[6]=b1.z; b[7]=b1.w;
            #pragma unroll
            for (int i = 0; i < TM; i++)
                #pragma unroll
                for (int j = 0; j < TN; j++)
                    acc[i][j] = fmaf(a[i], b[j], acc[i][j]);
        }
        __syncthreads();
    }

    #pragma unroll
    for (int i = 0; i < TM; i++) {
        long crow = rowBlock + ty * TM + i;
        float* cp = &C[crow * (long)N + colBlock + tx * TN];
        float4 v0, v1;
        v0.x = acc[i][0] + biasv; v0.y = acc[i][1] + biasv;
        v0.z = acc[i][2] + biasv; v0.w = acc[i][3] + biasv;
        v1.x = acc[i][4] + biasv; v1.y = acc[i][5] + biasv;
        v1.z = acc[i][6] + biasv; v1.w = acc[i][7] + biasv;
        *reinterpret_cast<float4*>(cp)     = v0;
        *reinterpret_cast<float4*>(cp + 4) = v1;
    }
}

__inline__ __device__ float warpMax(float v) {
    #pragma unroll
    for (int o = 16; o > 0; o >>= 1) v = fmaxf(v, __shfl_xor_sync(0xffffffffu, v, o));
    return v;
}
__inline__ __device__ float warpSum(float v) {
    #pragma unroll
    for (int o = 16; o > 0; o >>= 1) v += __shfl_xor_sync(0xffffffffu, v, o);
    return v;
}

// In-place row softmax over 2048 columns. One block (256 thr) per row; 8 elems/thread.
__global__ __launch_bounds__(256) void softmax2048(float* __restrict__ S)
{
    __shared__ float red[8];
    float* base = S + (long)blockIdx.x * 2048;
    float4* b4 = reinterpret_cast<float4*>(base);

    float4 v0 = b4[threadIdx.x];
    float4 v1 = b4[threadIdx.x + 256];

    float m = fmaxf(fmaxf(fmaxf(v0.x, v0.y), fmaxf(v0.z, v0.w)),
                    fmaxf(fmaxf(v1.x, v1.y), fmaxf(v1.z, v1.w)));
    m = warpMax(m);
    const int wid = threadIdx.x >> 5, lid = threadIdx.x & 31;
    if (lid == 0) red[wid] = m;
    __syncthreads();
    float bm = red[0];
    #pragma unroll
    for (int i = 1; i < 8; i++) bm = fmaxf(bm, red[i]);
    __syncthreads();

    v0.x = __expf(v0.x - bm); v0.y = __expf(v0.y - bm);
    v0.z = __expf(v0.z - bm); v0.w = __expf(v0.w - bm);
    v1.x = __expf(v1.x - bm); v1.y = __expf(v1.y - bm);
    v1.z = __expf(v1.z - bm); v1.w = __expf(v1.w - bm);

    float s = (v0.x + v0.y) + (v0.z + v0.w) + (v1.x + v1.y) + (v1.z + v1.w);
    s = warpSum(s);
    if (lid == 0) red[wid] = s;
    __syncthreads();
    float bs = 0.f;
    #pragma unroll
    for (int i = 0; i < 8; i++) bs += red[i];
    const float inv = 1.0f / bs;

    v0.x *= inv; v0.y *= inv; v0.z *= inv; v0.w *= inv;
    v1.x *= inv; v1.y *= inv; v1.z *= inv; v1.w *= inv;
    b4[threadIdx.x]       = v0;
    b4[threadIdx.x + 256] = v1;
}

extern "C" void kernel_launch(void* const* d_in, const int* in_sizes, int n_in,
                              void* d_out, int out_size)
{
    const float* key   = (const float*)d_in[0];
    const float* query = (const float*)d_in[1];
    const float* value = (const float*)d_in[2];
    const float* W     = (const float*)d_in[3];
    const float* bias  = (const float*)d_in[4];

    float* weights = (float*)d_out;                          // [B, LQ, LK]
    float* ctx     = weights + (long)B_ * LQ_ * LK_;         // [B, LQ, DV]

    float* qW = nullptr;
    cudaGetSymbolAddress((void**)&qW, g_qW);

    // 1) qW = query @ W   : [16384,1024] = [16384,1024] x [1024,1024] (NN)
    gemm_tile<false, false><<<dim3(D_ / BN, (B_ * LQ_) / BM, 1), 256>>>(
        query, W, qW,
        B_ * LQ_, D_, D_,
        0, 0, 0, nullptr);

    // 2) scores = qW @ key^T + bias : per batch [2048,2048] = [2048,1024] x [2048,1024]^T (NT)
    gemm_tile<true, true><<<dim3(LK_ / BN, LQ_ / BM, B_), 256>>>(
        qW, key, weights,
        LQ_, LK_, D_,
        (long)LQ_ * D_, (long)LK_ * D_, (long)LQ_ * LK_, bias);

    // 3) softmax rows (in place in d_out weights region)
    softmax2048<<<B_ * LQ_, 256>>>(weights);

    // 4) ctx = weights @ value : per batch [2048,1024] = [2048,2048] x [2048,1024] (NN)
    gemm_tile<false, false><<<dim3(DV_ / BN, LQ_ / BM, B_), 256>>>(
        weights, value, ctx,
        LQ_, DV_, LK_,
        (long)LQ_ * LK_, (long)LK_ * DV_, (long)LQ_ * DV_, nullptr);
}

// round 3
// speedup vs baseline: 1.3576x; 1.3576x over previous
#include <cuda_runtime.h>
#include <cstdint>

#define B_   8
#define LQ_  2048
#define LK_  2048
#define D_   1024
#define DV_  1024

// ---------------- scratch (device globals; no runtime allocation) ----------------
__device__ float g_qW[(long)B_ * LQ_ * D_];   // query @ W        [B*LQ, D]
__device__ float g_kT[(long)B_ * D_ * LK_];   // key transposed   [B][D][LK]

// ---------------- helpers ----------------
__device__ __forceinline__ uint32_t smem_u32(const void* p) {
    uint32_t a;
    asm("{ .reg .u64 t; cvta.to.shared.u64 t, %1; cvt.u32.u64 %0, t; }" : "=r"(a) : "l"(p));
    return a;
}

__device__ __forceinline__ uint32_t f2tf32(float x) {
    uint32_t u;
    asm("cvt.rna.tf32.f32 %0, %1;" : "=r"(u) : "f"(x));
    return u;
}

// split fp32 -> (tf32 hi, tf32 lo) with hi + lo ~= x to ~22 mantissa bits
__device__ __forceinline__ void split_tf32(float x, uint32_t& h, uint32_t& l) {
    h = f2tf32(x);
    l = f2tf32(x - __uint_as_float(h));
}

__device__ __forceinline__ void mma_tf32(float* d, const uint32_t* a, const uint32_t* b) {
    asm volatile(
        "mma.sync.aligned.m16n8k8.row.col.f32.tf32.tf32.f32 "
        "{%0,%1,%2,%3}, {%4,%5,%6,%7}, {%8,%9}, {%0,%1,%2,%3};"
        : "+f"(d[0]), "+f"(d[1]), "+f"(d[2]), "+f"(d[3])
        : "r"(a[0]), "r"(a[1]), "r"(a[2]), "r"(a[3]),
          "r"(b[0]), "r"(b[1]));
}

__device__ __forceinline__ void cp_async16(uint32_t saddr, const void* gaddr) {
    asm volatile("cp.async.cg.shared.global [%0], [%1], 16;" :: "r"(saddr), "l"(gaddr));
}
#define CP_COMMIT() asm volatile("cp.async.commit_group;" ::: "memory")
#define CP_WAIT(n)  asm volatile("cp.async.wait_group %0;" :: "n"(n) : "memory")

// ---------------- GEMM config ----------------
#define BM 128
#define BN 128
#define BK 32
#define STAGES 3
#define LDA_S 36                        // 32 + 4 pad (floats)
#define LDB_S 132                       // 128 + 4 pad (floats)
#define A_FLOATS (BM * LDA_S)           // 4608
#define B_FLOATS (BK * LDB_S)           // 4224
#define STAGE_FLOATS (A_FLOATS + B_FLOATS)
#define GEMM_SMEM (STAGES * STAGE_FLOATS * 4)

// C[M,N] = A[M,K] @ B[K,N], fp32 in / fp32 out, 3xTF32 tensor-core emulation.
// A row-major [M,K], B row-major [K,N]. Batched via blockIdx.z strides.
__global__ __launch_bounds__(256, 1) void gemm3x_tf32(
    const float* __restrict__ A, const float* __restrict__ Bm, float* __restrict__ C,
    int M, int N, int K, long sA, long sB, long sC)
{
    extern __shared__ float sf[];
    const uint32_t sbase = smem_u32(sf);

    A  += (long)blockIdx.z * sA;
    Bm += (long)blockIdx.z * sB;
    C  += (long)blockIdx.z * sC;

    const int tid  = threadIdx.x;
    const int lane = tid & 31;
    const int warp = tid >> 5;
    const int g    = lane >> 2;   // groupID (0..7)
    const int t    = lane & 3;    // threadID_in_group (0..3)
    const int wm   = (warp >> 2) * 64;   // warp M offset (0/64)
    const int wn   = (warp & 3) * 32;    // warp N offset (0/32/64/96)
    const int m0   = blockIdx.y * BM;
    const int n0   = blockIdx.x * BN;

    // ---- cp.async stage loader ----
    // A tile: 128 rows x 32 floats = 1024 16B-chunks; idx -> row=idx>>3, cc=idx&7
    // B tile:  32 rows x 128 floats = 1024 16B-chunks; idx -> row=idx>>5, cc=idx&31
    auto load_stage = [&](int buf, int k0) {
        const uint32_t sA0 = sbase + (uint32_t)(buf * STAGE_FLOATS) * 4u;
        const uint32_t sB0 = sA0 + (uint32_t)A_FLOATS * 4u;
        #pragma unroll
        for (int i = 0; i < 4; i++) {
            const int ci = tid + i * 256;
            {
                const int r = ci >> 3, cc = ci & 7;
                cp_async16(sA0 + (uint32_t)(r * LDA_S + cc * 4) * 4u,
                           A + (long)(m0 + r) * K + k0 + cc * 4);
            }
            {
                const int r = ci >> 5, cc = ci & 31;
                cp_async16(sB0 + (uint32_t)(r * LDB_S + cc * 4) * 4u,
                           Bm + (long)(k0 + r) * N + n0 + cc * 4);
            }
        }
        CP_COMMIT();
    };

    float acc[64];
    #pragma unroll
    for (int i = 0; i < 64; i++) acc[i] = 0.0f;

    const int iters = K / BK;

    load_stage(0, 0);
    load_stage(1, BK);

    for (int it = 0; it < iters; it++) {
        CP_WAIT(1);               // stage `it` ready (at most stage it+1 in flight)
        __syncthreads();          // all warps done with buffer (it-1)%3 (== (it+2)%3)

        if (it + 2 < iters) load_stage((it + 2) % STAGES, (it + 2) * BK);

        const float* As = sf + (it % STAGES) * STAGE_FLOATS;
        const float* Bs = As + A_FLOATS;

        #pragma unroll
        for (int kk = 0; kk < BK; kk += 8) {
            uint32_t ah[16], al[16], bh[8], bl[8];
            #pragma unroll
            for (int mi = 0; mi < 4; mi++) {
                const int r = wm + mi * 16 + g;
                split_tf32(As[r * LDA_S + kk + t],           ah[mi * 4 + 0], al[mi * 4 + 0]);
                split_tf32(As[(r + 8) * LDA_S + kk + t],     ah[mi * 4 + 1], al[mi * 4 + 1]);
                split_tf32(As[r * LDA_S + kk + t + 4],       ah[mi * 4 + 2], al[mi * 4 + 2]);
                split_tf32(As[(r + 8) * LDA_S + kk + t + 4], ah[mi * 4 + 3], al[mi * 4 + 3]);
            }
            #pragma unroll
            for (int nj = 0; nj < 4; nj++) {
                const int c = wn + nj * 8 + g;
                split_tf32(Bs[(kk + t) * LDB_S + c],       bh[nj * 2 + 0], bl[nj * 2 + 0]);
                split_tf32(Bs[(kk + t + 4) * LDB_S + c],   bh[nj * 2 + 1], bl[nj * 2 + 1]);
            }
            #pragma unroll
            for (int mi = 0; mi < 4; mi++)
                #pragma unroll
                for (int nj = 0; nj < 4; nj++) {
                    float* d = acc + (mi * 4 + nj) * 4;
                    mma_tf32(d, &ah[mi * 4], &bh[nj * 2]);   // hi*hi
                    mma_tf32(d, &ah[mi * 4], &bl[nj * 2]);   // hi*lo
                    mma_tf32(d, &al[mi * 4], &bh[nj * 2]);   // lo*hi
                }
        }
        __syncthreads();
    }

    // ---- epilogue: direct fp32 stores ----
    #pragma unroll
    for (int mi = 0; mi < 4; mi++) {
        #pragma unroll
        for (int nj = 0; nj < 4; nj++) {
            const float* d = acc + (mi * 4 + nj) * 4;
            const long row = m0 + wm + mi * 16 + g;
            const long col = n0 + wn + nj * 8 + 2 * t;
            *reinterpret_cast<float2*>(C + row * N + col)       = make_float2(d[0], d[1]);
            *reinterpret_cast<float2*>(C + (row + 8) * N + col) = make_float2(d[2], d[3]);
        }
    }
}

// ---------------- transpose: in[R,C] -> out[C,R], batched ----------------
__global__ __launch_bounds__(256) void transpose_f32(
    const float* __restrict__ in, float* __restrict__ out,
    int R, int C, long sIn, long sOut)
{
    __shared__ float tb[32][33];
    const float* ip = in + (long)blockIdx.z * sIn;
    float* op = out + (long)blockIdx.z * sOut;
    const int c0 = blockIdx.x * 32;
    const int r0 = blockIdx.y * 32;
    const int tx = threadIdx.x;   // 0..31
    const int ty = threadIdx.y;   // 0..7

    #pragma unroll
    for (int i = 0; i < 4; i++)
        tb[ty + 8 * i][tx] = ip[(long)(r0 + ty + 8 * i) * C + c0 + tx];
    __syncthreads();

    #pragma unroll
    for (int i = 0; i < 4; i++) {
        const int orow = ty + 8 * i;
        op[(long)(c0 + orow) * R + r0 + tx] = tb[tx][orow];
    }
}

// ---------------- softmax over 2048 cols, in place ----------------
__inline__ __device__ float warpMax(float v) {
    #pragma unroll
    for (int o = 16; o > 0; o >>= 1) v = fmaxf(v, __shfl_xor_sync(0xffffffffu, v, o));
    return v;
}
__inline__ __device__ float warpSum(float v) {
    #pragma unroll
    for (int o = 16; o > 0; o >>= 1) v += __shfl_xor_sync(0xffffffffu, v, o);
    return v;
}

__global__ __launch_bounds__(256) void softmax2048(float* __restrict__ S)
{
    __shared__ float red[8];
    float4* b4 = reinterpret_cast<float4*>(S + (long)blockIdx.x * 2048);

    float4 v0 = b4[threadIdx.x];
    float4 v1 = b4[threadIdx.x + 256];

    float m = fmaxf(fmaxf(fmaxf(v0.x, v0.y), fmaxf(v0.z, v0.w)),
                    fmaxf(fmaxf(v1.x, v1.y), fmaxf(v1.z, v1.w)));
    m = warpMax(m);
    const int wid = threadIdx.x >> 5, lid = threadIdx.x & 31;
    if (lid == 0) red[wid] = m;
    __syncthreads();
    float bm = red[0];
    #pragma unroll
    for (int i = 1; i < 8; i++) bm = fmaxf(bm, red[i]);
    __syncthreads();

    v0.x = __expf(v0.x - bm); v0.y = __expf(v0.y - bm);
    v0.z = __expf(v0.z - bm); v0.w = __expf(v0.w - bm);
    v1.x = __expf(v1.x - bm); v1.y = __expf(v1.y - bm);
    v1.z = __expf(v1.z - bm); v1.w = __expf(v1.w - bm);

    float s = (v0.x + v0.y) + (v0.z + v0.w) + (v1.x + v1.y) + (v1.z + v1.w);
    s = warpSum(s);
    if (lid == 0) red[wid] = s;
    __syncthreads();
    float bs = 0.f;
    #pragma unroll
    for (int i = 0; i < 8; i++) bs += red[i];
    const float inv = 1.0f / bs;

    v0.x *= inv; v0.y *= inv; v0.z *= inv; v0.w *= inv;
    v1.x *= inv; v1.y *= inv; v1.z *= inv; v1.w *= inv;
    b4[threadIdx.x]       = v0;
    b4[threadIdx.x + 256] = v1;
}

// ---------------- launch ----------------
extern "C" void kernel_launch(void* const* d_in, const int* in_sizes, int n_in,
                              void* d_out, int out_size)
{
    const float* key   = (const float*)d_in[0];
    const float* query = (const float*)d_in[1];
    const float* value = (const float*)d_in[2];
    const float* W     = (const float*)d_in[3];
    // bias (d_in[4]): scalar added to every score -> softmax-invariant -> no effect
    // on either output; intentionally unused.

    float* weights = (float*)d_out;                   // [B, LQ, LK]
    float* ctx     = weights + (long)B_ * LQ_ * LK_;  // [B, LQ, DV]

    float *qW, *kT;
    cudaGetSymbolAddress((void**)&qW, g_qW);
    cudaGetSymbolAddress((void**)&kT, g_kT);

    cudaFuncSetAttribute(gemm3x_tf32, cudaFuncAttributeMaxDynamicSharedMemorySize, GEMM_SMEM);

    // 0) kT[b][e][lk] = key[b][lk][e]
    transpose_f32<<<dim3(D_ / 32, LK_ / 32, B_), dim3(32, 8)>>>(
        key, kT, LK_, D_, (long)LK_ * D_, (long)D_ * LK_);

    // 1) qW = query @ W : [16384,1024] x [1024,1024]
    gemm3x_tf32<<<dim3(D_ / BN, (B_ * LQ_) / BM, 1), 256, GEMM_SMEM>>>(
        query, W, qW, B_ * LQ_, D_, D_, 0, 0, 0);

    // 2) scores = qW @ kT (per batch): [2048,1024] x [1024,2048] -> weights region
    gemm3x_tf32<<<dim3(LK_ / BN, LQ_ / BM, B_), 256, GEMM_SMEM>>>(
        qW, kT, weights, LQ_, LK_, D_,
        (long)LQ_ * D_, (long)D_ * LK_, (long)LQ_ * LK_);

    // 3) softmax rows in place
    softmax2048<<<B_ * LQ_, 256>>>(weights);

    // 4) ctx = weights @ value (per batch): [2048,2048] x [2048,1024]
    gemm3x_tf32<<<dim3(DV_ / BN, LQ_ / BM, B_), 256, GEMM_SMEM>>>(
        weights, value, ctx, LQ_, DV_, LK_,
        (long)LQ_ * LK_, (long)LK_ * DV_, (long)LQ_ * DV_);
}